// round 1
// baseline (speedup 1.0000x reference)
#include <cuda_runtime.h>
#include <math.h>

#define NB 8
#define C 192
#define C3 576
#define NH 4
#define CH 48
#define HH 128
#define WW 128
#define HW 16384
#define SPLIT 8
#define PART_STRIDE (CH*CH + 2*CH)   /* 2400 */

// Scratch (device globals: no allocation allowed in kernel_launch)
__device__ float g_qkv [NB*C3*HW];                 // 302 MB: 1x1 conv output
__device__ float g_dw  [NB*C3*HW];                 // 302 MB: depthwise output
__device__ float g_attn[NB*C*HW];                  // 100 MB: attention output
__device__ float g_part[SPLIT*NB*NH*PART_STRIDE];  // split-K partials (scores + sumsq)
__device__ float g_score[NB*NH*CH*CH];             // softmaxed scores

// ---------------------------------------------------------------------------
// Generic SGEMM: C[b] = A * B[b], A row-major [M,K], B[b] row-major [K,N].
// BM=128, BN=128, BK=16, 256 threads, 8x8 per-thread tile. M-guards for 576/192.
// ---------------------------------------------------------------------------
__global__ __launch_bounds__(256) void gemm_kernel(
    const float* __restrict__ A, const float* __restrict__ Bm, float* __restrict__ Cm,
    int M, int N, int K)
{
    const int BM = 128, BN = 128, BK = 16;
    __shared__ float As[BM][BK + 1];
    __shared__ float Bs[BK][BN];

    int tid = threadIdx.x;
    int tx = tid & 15, ty = tid >> 4;
    int m0 = blockIdx.y * BM, n0 = blockIdx.x * BN;
    const float* Bb = Bm + (size_t)blockIdx.z * K * N;
    float*       Cb = Cm + (size_t)blockIdx.z * M * N;

    float acc[8][8];
#pragma unroll
    for (int i = 0; i < 8; i++)
#pragma unroll
        for (int j = 0; j < 8; j++) acc[i][j] = 0.f;

    for (int k0 = 0; k0 < K; k0 += BK) {
        // A tile: 128x16 (guarded on M)
#pragma unroll
        for (int i = 0; i < 8; i++) {
            int idx = tid + i * 256;
            int r = idx >> 4, c = idx & 15;
            int m = m0 + r;
            As[r][c] = (m < M) ? A[(size_t)m * K + k0 + c] : 0.f;
        }
        // B tile: 16x128 via float4 (N=16384 always divisible)
#pragma unroll
        for (int i = 0; i < 2; i++) {
            int idx = tid + i * 256;         // float4 index, 512 total
            int r = idx >> 5, c = idx & 31;
            *(float4*)&Bs[r][c * 4] =
                *(const float4*)&Bb[(size_t)(k0 + r) * N + n0 + c * 4];
        }
        __syncthreads();

#pragma unroll
        for (int kk = 0; kk < BK; kk++) {
            float a[8], b[8];
#pragma unroll
            for (int i = 0; i < 8; i++) a[i] = As[ty * 8 + i][kk];
            *(float4*)&b[0] = *(float4*)&Bs[kk][tx * 4];
            *(float4*)&b[4] = *(float4*)&Bs[kk][64 + tx * 4];
#pragma unroll
            for (int i = 0; i < 8; i++)
#pragma unroll
                for (int j = 0; j < 8; j++) acc[i][j] += a[i] * b[j];
        }
        __syncthreads();
    }

#pragma unroll
    for (int i = 0; i < 8; i++) {
        int m = m0 + ty * 8 + i;
        if (m < M) {
            *(float4*)&Cb[(size_t)m * N + n0 + tx * 4]      = *(float4*)&acc[i][0];
            *(float4*)&Cb[(size_t)m * N + n0 + 64 + tx * 4] = *(float4*)&acc[i][4];
        }
    }
}

// ---------------------------------------------------------------------------
// Depthwise 3x3, SAME zero padding. One block per (row, b*channel).
// ---------------------------------------------------------------------------
__global__ __launch_bounds__(128) void dw_kernel(
    const float* __restrict__ in, float* __restrict__ out, const float* __restrict__ wdw)
{
    int y  = blockIdx.x;           // 0..127
    int bc = blockIdx.y;           // 0..NB*C3-1
    int ch = bc % C3;
    int tid = threadIdx.x;         // 0..127 == x

    __shared__ float srow[3][WW + 2];
    const float* base = in + (size_t)bc * HW;
#pragma unroll
    for (int r = 0; r < 3; r++) {
        int yy = y + r - 1;
        srow[r][tid + 1] = (yy >= 0 && yy < HH) ? base[yy * WW + tid] : 0.f;
    }
    if (tid == 0) {
#pragma unroll
        for (int r = 0; r < 3; r++) { srow[r][0] = 0.f; srow[r][WW + 1] = 0.f; }
    }
    __syncthreads();

    const float* w = wdw + ch * 9;
    float s = 0.f;
#pragma unroll
    for (int r = 0; r < 3; r++)
#pragma unroll
        for (int dx = 0; dx < 3; dx++)
            s += w[r * 3 + dx] * srow[r][tid + dx];
    out[(size_t)bc * HW + y * WW + tid] = s;
}

// ---------------------------------------------------------------------------
// Score partials: per (split, b, head) accumulate 48x48 Q.K^T over an s-range,
// plus per-row sum-of-squares for q and k (for L2 norm).
// ---------------------------------------------------------------------------
__global__ __launch_bounds__(256) void score_partial_kernel(const float* __restrict__ qkvd)
{
    int split = blockIdx.x;
    int unit  = blockIdx.y;                 // b*NH + head
    int b = unit >> 2, hd = unit & 3;
    const float* qb = qkvd + ((size_t)b * C3 + hd * CH) * HW;
    const float* kb = qb + (size_t)C * HW;

    const int CS = 32;
    __shared__ float qs[CH][CS + 1], ks[CH][CS + 1];

    int tid = threadIdx.x, tx = tid & 15, ty = tid >> 4;
    float acc[3][3] = {{0.f,0.f,0.f},{0.f,0.f,0.f},{0.f,0.f,0.f}};
    float nacc = 0.f;

    int s_beg = split * (HW / SPLIT);
    int s_end = s_beg + (HW / SPLIT);
    for (int s0 = s_beg; s0 < s_end; s0 += CS) {
#pragma unroll
        for (int i = 0; i < (CH * CS) / 256; i++) {   // 6 iters
            int idx = tid + i * 256;
            int r = idx >> 5, c = idx & 31;
            qs[r][c] = qb[(size_t)r * HW + s0 + c];
            ks[r][c] = kb[(size_t)r * HW + s0 + c];
        }
        __syncthreads();

        if (tid < 2 * CH) {
            int r = (tid < CH) ? tid : (tid - CH);
            const float* row = (tid < CH) ? qs[r] : ks[r];
#pragma unroll
            for (int j = 0; j < CS; j++) { float v = row[j]; nacc += v * v; }
        }

#pragma unroll 4
        for (int j = 0; j < CS; j++) {
            float q0 = qs[3 * ty + 0][j], q1 = qs[3 * ty + 1][j], q2 = qs[3 * ty + 2][j];
            float k0 = ks[3 * tx + 0][j], k1 = ks[3 * tx + 1][j], k2 = ks[3 * tx + 2][j];
            acc[0][0] += q0 * k0; acc[0][1] += q0 * k1; acc[0][2] += q0 * k2;
            acc[1][0] += q1 * k0; acc[1][1] += q1 * k1; acc[1][2] += q1 * k2;
            acc[2][0] += q2 * k0; acc[2][1] += q2 * k1; acc[2][2] += q2 * k2;
        }
        __syncthreads();
    }

    float* part = g_part + ((size_t)split * NB * NH + unit) * PART_STRIDE;
#pragma unroll
    for (int i = 0; i < 3; i++)
#pragma unroll
        for (int j = 0; j < 3; j++)
            part[(3 * ty + i) * CH + (3 * tx + j)] = acc[i][j];
    if (tid < 2 * CH) part[CH * CH + tid] = nacc;
}

// ---------------------------------------------------------------------------
// Reduce partials, apply 1/(|q||k|) * temperature, row softmax. 32 blocks.
// ---------------------------------------------------------------------------
__global__ __launch_bounds__(256) void softmax_kernel(const float* __restrict__ temperature)
{
    int unit = blockIdx.x;
    int hd = unit & 3;
    __shared__ float S[CH][CH];
    __shared__ float rq[CH], rk[CH];
    int tid = threadIdx.x;

    for (int e = tid; e < CH * CH; e += 256) {
        float s = 0.f;
#pragma unroll
        for (int p = 0; p < SPLIT; p++)
            s += g_part[((size_t)p * NB * NH + unit) * PART_STRIDE + e];
        S[e / CH][e % CH] = s;
    }
    if (tid < 2 * CH) {
        float s = 0.f;
#pragma unroll
        for (int p = 0; p < SPLIT; p++)
            s += g_part[((size_t)p * NB * NH + unit) * PART_STRIDE + CH * CH + tid];
        float inv = 1.f / fmaxf(sqrtf(s), 1e-12f);
        if (tid < CH) rq[tid] = inv; else rk[tid - CH] = inv;
    }
    __syncthreads();

    float temp = temperature[hd];
    if (tid < CH) {
        int i = tid;
        float row[CH];
        float mx = -3.402823466e38f;
#pragma unroll
        for (int j = 0; j < CH; j++) {
            float v = S[i][j] * rq[i] * rk[j] * temp;
            row[j] = v;
            mx = fmaxf(mx, v);
        }
        float sum = 0.f;
#pragma unroll
        for (int j = 0; j < CH; j++) { row[j] = expf(row[j] - mx); sum += row[j]; }
        float inv = 1.f / sum;
#pragma unroll
        for (int j = 0; j < CH; j++)
            g_score[(size_t)unit * CH * CH + i * CH + j] = row[j] * inv;
    }
}

// ---------------------------------------------------------------------------
// out[c,s] = sum_d score[c,d] * v[d,s].  Grid (HW/128 tiles, 32 units).
// ---------------------------------------------------------------------------
__global__ __launch_bounds__(256) void attnout_kernel(const float* __restrict__ qkvd)
{
    const int TS = 128;
    int unit = blockIdx.y;
    int b = unit >> 2, hd = unit & 3;
    int s0 = blockIdx.x * TS;
    const float* vb = qkvd + ((size_t)b * C3 + 2 * C + hd * CH) * HW;
    float* ob = g_attn + ((size_t)b * C + hd * CH) * HW;

    __shared__ float sc[CH][CH];
    __shared__ float vs[CH][TS];
    int tid = threadIdx.x, tx = tid & 15, ty = tid >> 4;

    for (int e = tid; e < CH * CH; e += 256)
        sc[e / CH][e % CH] = g_score[(size_t)unit * CH * CH + e];
    for (int idx = tid; idx < CH * TS / 4; idx += 256) {   // float4 loads
        int r = idx >> 5, c = idx & 31;
        *(float4*)&vs[r][c * 4] = *(const float4*)&vb[(size_t)r * HW + s0 + c * 4];
    }
    __syncthreads();

    float acc[3][8];
#pragma unroll
    for (int i = 0; i < 3; i++)
#pragma unroll
        for (int j = 0; j < 8; j++) acc[i][j] = 0.f;

#pragma unroll 4
    for (int d = 0; d < CH; d++) {
        float a0 = sc[3 * ty + 0][d], a1 = sc[3 * ty + 1][d], a2 = sc[3 * ty + 2][d];
        float bv[8];
        *(float4*)&bv[0] = *(float4*)&vs[d][tx * 4];
        *(float4*)&bv[4] = *(float4*)&vs[d][64 + tx * 4];
#pragma unroll
        for (int j = 0; j < 8; j++) {
            acc[0][j] += a0 * bv[j];
            acc[1][j] += a1 * bv[j];
            acc[2][j] += a2 * bv[j];
        }
    }

#pragma unroll
    for (int i = 0; i < 3; i++) {
        int cch = 3 * ty + i;
        *(float4*)&ob[(size_t)cch * HW + s0 + tx * 4]      = *(float4*)&acc[i][0];
        *(float4*)&ob[(size_t)cch * HW + s0 + 64 + tx * 4] = *(float4*)&acc[i][4];
    }
}

// ---------------------------------------------------------------------------
extern "C" void kernel_launch(void* const* d_in, const int* in_sizes, int n_in,
                              void* d_out, int out_size)
{
    (void)in_sizes; (void)n_in; (void)out_size;
    const float* x      = (const float*)d_in[0];
    const float* w_qkv  = (const float*)d_in[1];
    const float* w_dw   = (const float*)d_in[2];
    const float* w_proj = (const float*)d_in[3];
    const float* temp   = (const float*)d_in[4];
    float* out = (float*)d_out;

    float *qkv, *dwb, *attn;
    cudaGetSymbolAddress((void**)&qkv,  g_qkv);
    cudaGetSymbolAddress((void**)&dwb,  g_dw);
    cudaGetSymbolAddress((void**)&attn, g_attn);

    // 1) qkv = W_qkv (576x192) * x[b] (192x16384)
    gemm_kernel<<<dim3(HW / 128, (C3 + 127) / 128, NB), 256>>>(w_qkv, x, qkv, C3, HW, C);
    // 2) depthwise 3x3
    dw_kernel<<<dim3(HH, NB * C3), 128>>>(qkv, dwb, w_dw);
    // 3) split-K score partials
    score_partial_kernel<<<dim3(SPLIT, NB * NH), 256>>>(dwb);
    // 4) normalize + temperature + softmax
    softmax_kernel<<<NB * NH, 256>>>(temp);
    // 5) attention output = score @ v
    attnout_kernel<<<dim3(HW / 128, NB * NH), 256>>>(dwb);
    // 6) out = W_proj (192x192) * attn[b]
    gemm_kernel<<<dim3(HW / 128, (C + 127) / 128, NB), 256>>>(w_proj, attn, out, C, HW, C);
}

// round 2
// speedup vs baseline: 1.7276x; 1.7276x over previous
#include <cuda_runtime.h>
#include <math.h>

#define NB 8
#define C 192
#define C3 576
#define NH 4
#define CH 48
#define HH 128
#define WW 128
#define HW 16384
#define SPLIT 8
#define PART_STRIDE (CH*CH + 2*CH)   /* 2400 */

// Scratch (device globals: no allocation allowed in kernel_launch)
__device__ float g_qkv [NB*C3*HW];                 // 302 MB: 1x1 conv output
__device__ float g_dw  [NB*C3*HW];                 // 302 MB: depthwise output
__device__ float g_attn[NB*C*HW];                  // 100 MB: attention output
__device__ float g_part[SPLIT*NB*NH*PART_STRIDE];  // split-K partials
__device__ float g_score[NB*NH*CH*CH];             // softmaxed scores

// ===========================================================================
// Tensor-core TF32 GEMM: C[b] = A * B[b]
// A [M,K=192] row-major (weights), B [192,N] row-major, C [M,N].
// BM=64, BN=128, BK=32, 256 threads (8 warps 2x4), warp tile 32x32.
// mma.sync.aligned.m16n8k8.row.col.f32.tf32.tf32.f32
// ===========================================================================
#define GBM 64
#define GBN 128
#define GBK 32
#define KD  192
#define GNT (KD/GBK)   /* 6 */
#define SA  36         /* As[m][k] stride: conflict-free a-frag loads */

__device__ __forceinline__ unsigned f2tf(float f) {
    unsigned u; asm("cvt.rna.tf32.f32 %0, %1;" : "=r"(u) : "f"(f)); return u;
}

#define MMA_TF32(d, av, bv)                                                   \
  asm("mma.sync.aligned.m16n8k8.row.col.f32.tf32.tf32.f32 "                   \
      "{%0,%1,%2,%3}, {%4,%5,%6,%7}, {%8,%9}, {%0,%1,%2,%3};"                 \
      : "+f"(d[0]), "+f"(d[1]), "+f"(d[2]), "+f"(d[3])                        \
      : "r"(av[0]), "r"(av[1]), "r"(av[2]), "r"(av[3]),                       \
        "r"(bv[0]), "r"(bv[1]))

__global__ __launch_bounds__(256) void gemm_tf32_kernel(
    const float* __restrict__ A, const float* __restrict__ Bm, float* __restrict__ Cm,
    int M, int N)
{
    __shared__ unsigned As[GBM * SA];     // [m][k], stride 36
    __shared__ unsigned Bs[GBK * GBN];    // [k][n], XOR-8 swizzled on n

    const int tid  = threadIdx.x;
    const int lane = tid & 31, wid = tid >> 5;
    const int wm = wid & 1, wn = wid >> 1;       // 2 x 4 warps
    const int g = lane >> 2, tig = lane & 3;

    const int m0 = blockIdx.y * GBM, n0 = blockIdx.x * GBN;
    const float* Ab = A + (size_t)m0 * KD;
    const float* Bb = Bm + (size_t)blockIdx.z * KD * N + n0;
    float*       Cb = Cm + (size_t)blockIdx.z * M * N;

    float acc[2][4][4];
#pragma unroll
    for (int mi = 0; mi < 2; mi++)
#pragma unroll
        for (int ni = 0; ni < 4; ni++)
#pragma unroll
            for (int j = 0; j < 4; j++) acc[mi][ni][j] = 0.f;

    // ---- register prefetch state ----
    float4 areg[2];   // A: 2 float4 per thread (64x32 tile)
    float4 breg[4];   // B: 4 float4 per thread (32x128 tile)

    // A load coords: idx = tid*2+i -> row = idx>>3, kc = (idx&7)*4
    // B load coords: idx = tid+i*256 -> row = idx>>5, c4 = idx&31

    // prologue: tile 0
#pragma unroll
    for (int i = 0; i < 2; i++) {
        int idx = tid * 2 + i, row = idx >> 3, kc = (idx & 7) * 4;
        areg[i] = *(const float4*)&Ab[(size_t)row * KD + kc];
    }
#pragma unroll
    for (int i = 0; i < 4; i++) {
        int idx = tid + i * 256, row = idx >> 5, c4 = idx & 31;
        breg[i] = *(const float4*)&Bb[(size_t)row * N + c4 * 4];
    }
#pragma unroll
    for (int i = 0; i < 2; i++) {
        int idx = tid * 2 + i, row = idx >> 3, kc = (idx & 7) * 4;
        As[row * SA + kc + 0] = f2tf(areg[i].x);
        As[row * SA + kc + 1] = f2tf(areg[i].y);
        As[row * SA + kc + 2] = f2tf(areg[i].z);
        As[row * SA + kc + 3] = f2tf(areg[i].w);
    }
#pragma unroll
    for (int i = 0; i < 4; i++) {
        int idx = tid + i * 256, row = idx >> 5, c4 = idx & 31;
        int col = (c4 * 4) ^ ((row & 3) * 8);
        uint4 v = make_uint4(f2tf(breg[i].x), f2tf(breg[i].y), f2tf(breg[i].z), f2tf(breg[i].w));
        *(uint4*)&Bs[row * GBN + col] = v;
    }
    __syncthreads();

    for (int t = 0; t < GNT; t++) {
        if (t + 1 < GNT) {
            int kofs = (t + 1) * GBK;
#pragma unroll
            for (int i = 0; i < 4; i++) {
                int idx = tid + i * 256, row = idx >> 5, c4 = idx & 31;
                breg[i] = *(const float4*)&Bb[(size_t)(kofs + row) * N + c4 * 4];
            }
#pragma unroll
            for (int i = 0; i < 2; i++) {
                int idx = tid * 2 + i, row = idx >> 3, kc = (idx & 7) * 4;
                areg[i] = *(const float4*)&Ab[(size_t)row * KD + kofs + kc];
            }
        }

        // ---- compute on current tiles ----
#pragma unroll
        for (int kk = 0; kk < 4; kk++) {
            unsigned a[2][4], b[4][2];
            const unsigned* Ap = As + (wm * 32 + g) * SA + kk * 8 + tig;
#pragma unroll
            for (int mi = 0; mi < 2; mi++) {
                a[mi][0] = Ap[(mi * 16) * SA];
                a[mi][1] = Ap[(mi * 16 + 8) * SA];
                a[mi][2] = Ap[(mi * 16) * SA + 4];
                a[mi][3] = Ap[(mi * 16 + 8) * SA + 4];
            }
            const unsigned* Bp0 = Bs + (kk * 8 + tig) * GBN;
            const unsigned* Bp1 = Bs + (kk * 8 + tig + 4) * GBN;
            const int cb = wn * 32 + g, sw = tig * 8;
#pragma unroll
            for (int ni = 0; ni < 4; ni++) {
                b[ni][0] = Bp0[(cb + ni * 8) ^ sw];
                b[ni][1] = Bp1[(cb + ni * 8) ^ sw];
            }
#pragma unroll
            for (int mi = 0; mi < 2; mi++)
#pragma unroll
                for (int ni = 0; ni < 4; ni++)
                    MMA_TF32(acc[mi][ni], a[mi], b[ni]);
        }
        __syncthreads();

        if (t + 1 < GNT) {
#pragma unroll
            for (int i = 0; i < 4; i++) {
                int idx = tid + i * 256, row = idx >> 5, c4 = idx & 31;
                int col = (c4 * 4) ^ ((row & 3) * 8);
                uint4 v = make_uint4(f2tf(breg[i].x), f2tf(breg[i].y), f2tf(breg[i].z), f2tf(breg[i].w));
                *(uint4*)&Bs[row * GBN + col] = v;
            }
#pragma unroll
            for (int i = 0; i < 2; i++) {
                int idx = tid * 2 + i, row = idx >> 3, kc = (idx & 7) * 4;
                As[row * SA + kc + 0] = f2tf(areg[i].x);
                As[row * SA + kc + 1] = f2tf(areg[i].y);
                As[row * SA + kc + 2] = f2tf(areg[i].z);
                As[row * SA + kc + 3] = f2tf(areg[i].w);
            }
            __syncthreads();
        }
    }

    // ---- epilogue ----
#pragma unroll
    for (int mi = 0; mi < 2; mi++) {
        int m = m0 + wm * 32 + mi * 16 + g;
#pragma unroll
        for (int ni = 0; ni < 4; ni++) {
            int n = n0 + wn * 32 + ni * 8 + tig * 2;
            float2 v0 = make_float2(acc[mi][ni][0], acc[mi][ni][1]);
            float2 v1 = make_float2(acc[mi][ni][2], acc[mi][ni][3]);
            *(float2*)&Cb[(size_t)m * N + n]       = v0;
            *(float2*)&Cb[(size_t)(m + 8) * N + n] = v1;
        }
    }
}

// ---------------------------------------------------------------------------
// Depthwise 3x3, SAME zero padding. One block per (row, b*channel).
// ---------------------------------------------------------------------------
__global__ __launch_bounds__(128) void dw_kernel(
    const float* __restrict__ in, float* __restrict__ out, const float* __restrict__ wdw)
{
    int y  = blockIdx.x;
    int bc = blockIdx.y;
    int ch = bc % C3;
    int tid = threadIdx.x;

    __shared__ float srow[3][WW + 2];
    const float* base = in + (size_t)bc * HW;
#pragma unroll
    for (int r = 0; r < 3; r++) {
        int yy = y + r - 1;
        srow[r][tid + 1] = (yy >= 0 && yy < HH) ? base[yy * WW + tid] : 0.f;
    }
    if (tid == 0) {
#pragma unroll
        for (int r = 0; r < 3; r++) { srow[r][0] = 0.f; srow[r][WW + 1] = 0.f; }
    }
    __syncthreads();

    const float* w = wdw + ch * 9;
    float s = 0.f;
#pragma unroll
    for (int r = 0; r < 3; r++)
#pragma unroll
        for (int dx = 0; dx < 3; dx++)
            s += w[r * 3 + dx] * srow[r][tid + dx];
    out[(size_t)bc * HW + y * WW + tid] = s;
}

// ---------------------------------------------------------------------------
// Score partials: per (split, b, head) accumulate 48x48 Q.K^T over an s-range,
// plus per-row sum-of-squares for q and k.
// ---------------------------------------------------------------------------
__global__ __launch_bounds__(256) void score_partial_kernel(const float* __restrict__ qkvd)
{
    int split = blockIdx.x;
    int unit  = blockIdx.y;
    int b = unit >> 2, hd = unit & 3;
    const float* qb = qkvd + ((size_t)b * C3 + hd * CH) * HW;
    const float* kb = qb + (size_t)C * HW;

    const int CS = 32;
    __shared__ float qs[CH][CS + 1], ks[CH][CS + 1];

    int tid = threadIdx.x, tx = tid & 15, ty = tid >> 4;
    float acc[3][3] = {{0.f,0.f,0.f},{0.f,0.f,0.f},{0.f,0.f,0.f}};
    float nacc = 0.f;

    int s_beg = split * (HW / SPLIT);
    int s_end = s_beg + (HW / SPLIT);
    for (int s0 = s_beg; s0 < s_end; s0 += CS) {
#pragma unroll
        for (int i = 0; i < (CH * CS) / 256; i++) {
            int idx = tid + i * 256;
            int r = idx >> 5, c = idx & 31;
            qs[r][c] = qb[(size_t)r * HW + s0 + c];
            ks[r][c] = kb[(size_t)r * HW + s0 + c];
        }
        __syncthreads();

        if (tid < 2 * CH) {
            int r = (tid < CH) ? tid : (tid - CH);
            const float* row = (tid < CH) ? qs[r] : ks[r];
#pragma unroll
            for (int j = 0; j < CS; j++) { float v = row[j]; nacc += v * v; }
        }

#pragma unroll 4
        for (int j = 0; j < CS; j++) {
            float q0 = qs[3 * ty + 0][j], q1 = qs[3 * ty + 1][j], q2 = qs[3 * ty + 2][j];
            float k0 = ks[3 * tx + 0][j], k1 = ks[3 * tx + 1][j], k2 = ks[3 * tx + 2][j];
            acc[0][0] += q0 * k0; acc[0][1] += q0 * k1; acc[0][2] += q0 * k2;
            acc[1][0] += q1 * k0; acc[1][1] += q1 * k1; acc[1][2] += q1 * k2;
            acc[2][0] += q2 * k0; acc[2][1] += q2 * k1; acc[2][2] += q2 * k2;
        }
        __syncthreads();
    }

    float* part = g_part + ((size_t)split * NB * NH + unit) * PART_STRIDE;
#pragma unroll
    for (int i = 0; i < 3; i++)
#pragma unroll
        for (int j = 0; j < 3; j++)
            part[(3 * ty + i) * CH + (3 * tx + j)] = acc[i][j];
    if (tid < 2 * CH) part[CH * CH + tid] = nacc;
}

// ---------------------------------------------------------------------------
// Reduce partials, apply 1/(|q||k|) * temperature, row softmax. 32 blocks.
// ---------------------------------------------------------------------------
__global__ __launch_bounds__(256) void softmax_kernel(const float* __restrict__ temperature)
{
    int unit = blockIdx.x;
    int hd = unit & 3;
    __shared__ float S[CH][CH];
    __shared__ float rq[CH], rk[CH];
    int tid = threadIdx.x;

    for (int e = tid; e < CH * CH; e += 256) {
        float s = 0.f;
#pragma unroll
        for (int p = 0; p < SPLIT; p++)
            s += g_part[((size_t)p * NB * NH + unit) * PART_STRIDE + e];
        S[e / CH][e % CH] = s;
    }
    if (tid < 2 * CH) {
        float s = 0.f;
#pragma unroll
        for (int p = 0; p < SPLIT; p++)
            s += g_part[((size_t)p * NB * NH + unit) * PART_STRIDE + CH * CH + tid];
        float inv = 1.f / fmaxf(sqrtf(s), 1e-12f);
        if (tid < CH) rq[tid] = inv; else rk[tid - CH] = inv;
    }
    __syncthreads();

    float temp = temperature[hd];
    if (tid < CH) {
        int i = tid;
        float row[CH];
        float mx = -3.402823466e38f;
#pragma unroll
        for (int j = 0; j < CH; j++) {
            float v = S[i][j] * rq[i] * rk[j] * temp;
            row[j] = v;
            mx = fmaxf(mx, v);
        }
        float sum = 0.f;
#pragma unroll
        for (int j = 0; j < CH; j++) { row[j] = expf(row[j] - mx); sum += row[j]; }
        float inv = 1.f / sum;
#pragma unroll
        for (int j = 0; j < CH; j++)
            g_score[(size_t)unit * CH * CH + i * CH + j] = row[j] * inv;
    }
}

// ---------------------------------------------------------------------------
// out[c,s] = sum_d score[c,d] * v[d,s].  Grid (HW/128 tiles, 32 units).
// ---------------------------------------------------------------------------
__global__ __launch_bounds__(256) void attnout_kernel(const float* __restrict__ qkvd)
{
    const int TS = 128;
    int unit = blockIdx.y;
    int b = unit >> 2, hd = unit & 3;
    int s0 = blockIdx.x * TS;
    const float* vb = qkvd + ((size_t)b * C3 + 2 * C + hd * CH) * HW;
    float* ob = g_attn + ((size_t)b * C + hd * CH) * HW;

    __shared__ float sc[CH][CH];
    __shared__ float vs[CH][TS];
    int tid = threadIdx.x, tx = tid & 15, ty = tid >> 4;

    for (int e = tid; e < CH * CH; e += 256)
        sc[e / CH][e % CH] = g_score[(size_t)unit * CH * CH + e];
    for (int idx = tid; idx < CH * TS / 4; idx += 256) {
        int r = idx >> 5, c = idx & 31;
        *(float4*)&vs[r][c * 4] = *(const float4*)&vb[(size_t)r * HW + s0 + c * 4];
    }
    __syncthreads();

    float acc[3][8];
#pragma unroll
    for (int i = 0; i < 3; i++)
#pragma unroll
        for (int j = 0; j < 8; j++) acc[i][j] = 0.f;

#pragma unroll 4
    for (int d = 0; d < CH; d++) {
        float a0 = sc[3 * ty + 0][d], a1 = sc[3 * ty + 1][d], a2 = sc[3 * ty + 2][d];
        float bv[8];
        *(float4*)&bv[0] = *(float4*)&vs[d][tx * 4];
        *(float4*)&bv[4] = *(float4*)&vs[d][64 + tx * 4];
#pragma unroll
        for (int j = 0; j < 8; j++) {
            acc[0][j] += a0 * bv[j];
            acc[1][j] += a1 * bv[j];
            acc[2][j] += a2 * bv[j];
        }
    }

#pragma unroll
    for (int i = 0; i < 3; i++) {
        int cch = 3 * ty + i;
        *(float4*)&ob[(size_t)cch * HW + s0 + tx * 4]      = *(float4*)&acc[i][0];
        *(float4*)&ob[(size_t)cch * HW + s0 + 64 + tx * 4] = *(float4*)&acc[i][4];
    }
}

// ---------------------------------------------------------------------------
extern "C" void kernel_launch(void* const* d_in, const int* in_sizes, int n_in,
                              void* d_out, int out_size)
{
    (void)in_sizes; (void)n_in; (void)out_size;
    const float* x      = (const float*)d_in[0];
    const float* w_qkv  = (const float*)d_in[1];
    const float* w_dw   = (const float*)d_in[2];
    const float* w_proj = (const float*)d_in[3];
    const float* temp   = (const float*)d_in[4];
    float* out = (float*)d_out;

    float *qkv, *dwb, *attn;
    cudaGetSymbolAddress((void**)&qkv,  g_qkv);
    cudaGetSymbolAddress((void**)&dwb,  g_dw);
    cudaGetSymbolAddress((void**)&attn, g_attn);

    // 1) qkv = W_qkv (576x192) * x[b] (192x16384)  — TF32 tensor cores
    gemm_tf32_kernel<<<dim3(HW / GBN, C3 / GBM, NB), 256>>>(w_qkv, x, qkv, C3, HW);
    // 2) depthwise 3x3
    dw_kernel<<<dim3(HH, NB * C3), 128>>>(qkv, dwb, w_dw);
    // 3) split-K score partials
    score_partial_kernel<<<dim3(SPLIT, NB * NH), 256>>>(dwb);
    // 4) normalize + temperature + softmax
    softmax_kernel<<<NB * NH, 256>>>(temp);
    // 5) attention output = score @ v
    attnout_kernel<<<dim3(HW / 128, NB * NH), 256>>>(dwb);
    // 6) out = W_proj (192x192) * attn[b]  — TF32 tensor cores
    gemm_tf32_kernel<<<dim3(HW / GBN, C / GBM, NB), 256>>>(w_proj, attn, out, C, HW);
}

// round 4
// speedup vs baseline: 2.2798x; 1.3196x over previous
#include <cuda_runtime.h>
#include <math.h>

#define NB 8
#define C 192
#define C3 576
#define NH 4
#define CH 48
#define HH 128
#define WW 128
#define HW 16384
#define SPLIT 32
#define PART_STRIDE (CH*CH + 2*CH)   /* 2400 */

// Scratch (device globals: no allocation allowed in kernel_launch)
__device__ float g_qkv [NB*C3*HW];                 // 302 MB: 1x1 conv output
__device__ float g_dw  [NB*C3*HW];                 // 302 MB: depthwise output
__device__ float g_attn[NB*C*HW];                  // 100 MB: attention output
__device__ float g_part[SPLIT*NB*NH*PART_STRIDE];  // split-K partials
__device__ float g_score[NB*NH*CH*CH];             // softmaxed scores

// ===========================================================================
// Tensor-core TF32 GEMM: C[b] = A * B[b]
// A [M,K=192] row-major (weights), B [192,N] row-major, C [M,N].
// BM=64, BN=128, BK=32, 256 threads (8 warps 2x4), warp tile 32x32.
// Double-buffered smem (exactly 48KB): A stride-32 + XOR-4 row swizzle,
// B XOR-8 swizzle. One __syncthreads per k-tile.
// ===========================================================================
#define GBM 64
#define GBN 128
#define GBK 32
#define KD  192
#define GNT (KD/GBK)   /* 6 */

__device__ __forceinline__ unsigned f2tf(float f) {
    unsigned u; asm("cvt.rna.tf32.f32 %0, %1;" : "=r"(u) : "f"(f)); return u;
}

#define MMA_TF32(d, av, bv)                                                   \
  asm("mma.sync.aligned.m16n8k8.row.col.f32.tf32.tf32.f32 "                   \
      "{%0,%1,%2,%3}, {%4,%5,%6,%7}, {%8,%9}, {%0,%1,%2,%3};"                 \
      : "+f"(d[0]), "+f"(d[1]), "+f"(d[2]), "+f"(d[3])                        \
      : "r"(av[0]), "r"(av[1]), "r"(av[2]), "r"(av[3]),                       \
        "r"(bv[0]), "r"(bv[1]))

__global__ __launch_bounds__(256) void gemm_tf32_kernel(
    const float* __restrict__ A, const float* __restrict__ Bm, float* __restrict__ Cm,
    int M, int N)
{
    __shared__ unsigned As[2][GBM * GBK];    // [m][k^((m&7)*4)], stride 32
    __shared__ unsigned Bs[2][GBK * GBN];    // [k][n], XOR-8 swizzled on n

    const int tid  = threadIdx.x;
    const int lane = tid & 31, wid = tid >> 5;
    const int wm = wid & 1, wn = wid >> 1;       // 2 x 4 warps
    const int g = lane >> 2, tig = lane & 3;

    const int m0 = blockIdx.y * GBM, n0 = blockIdx.x * GBN;
    const float* Ab = A + (size_t)m0 * KD;
    const float* Bb = Bm + (size_t)blockIdx.z * KD * N + n0;
    float*       Cb = Cm + (size_t)blockIdx.z * M * N;

    float acc[2][4][4];
#pragma unroll
    for (int mi = 0; mi < 2; mi++)
#pragma unroll
        for (int ni = 0; ni < 4; ni++)
#pragma unroll
            for (int j = 0; j < 4; j++) acc[mi][ni][j] = 0.f;

    float4 areg[2];   // A: 2 float4 per thread (64x32 tile)
    float4 breg[4];   // B: 4 float4 per thread (32x128 tile)

    // A store: idx = tid*2+i -> row = idx>>3, kc = (idx&7)*4, col = kc ^ ((row&7)*4)
    // B store: idx = tid+i*256 -> row = idx>>5, c4 = idx&31, col = (c4*4) ^ ((row&3)*8)

    // prologue: LDG tile 0 + STS into buffer 0
#pragma unroll
    for (int i = 0; i < 2; i++) {
        int idx = tid * 2 + i, row = idx >> 3, kc = (idx & 7) * 4;
        areg[i] = *(const float4*)&Ab[(size_t)row * KD + kc];
    }
#pragma unroll
    for (int i = 0; i < 4; i++) {
        int idx = tid + i * 256, row = idx >> 5, c4 = idx & 31;
        breg[i] = *(const float4*)&Bb[(size_t)row * N + c4 * 4];
    }
#pragma unroll
    for (int i = 0; i < 2; i++) {
        int idx = tid * 2 + i, row = idx >> 3, kc = (idx & 7) * 4;
        int col = kc ^ ((row & 7) * 4);
        uint4 v = make_uint4(f2tf(areg[i].x), f2tf(areg[i].y), f2tf(areg[i].z), f2tf(areg[i].w));
        *(uint4*)&As[0][row * GBK + col] = v;
    }
#pragma unroll
    for (int i = 0; i < 4; i++) {
        int idx = tid + i * 256, row = idx >> 5, c4 = idx & 31;
        int col = (c4 * 4) ^ ((row & 3) * 8);
        uint4 v = make_uint4(f2tf(breg[i].x), f2tf(breg[i].y), f2tf(breg[i].z), f2tf(breg[i].w));
        *(uint4*)&Bs[0][row * GBN + col] = v;
    }
    __syncthreads();

#pragma unroll
    for (int t = 0; t < GNT; t++) {
        const int cur = t & 1;
        if (t + 1 < GNT) {
            int kofs = (t + 1) * GBK;
#pragma unroll
            for (int i = 0; i < 4; i++) {
                int idx = tid + i * 256, row = idx >> 5, c4 = idx & 31;
                breg[i] = *(const float4*)&Bb[(size_t)(kofs + row) * N + c4 * 4];
            }
#pragma unroll
            for (int i = 0; i < 2; i++) {
                int idx = tid * 2 + i, row = idx >> 3, kc = (idx & 7) * 4;
                areg[i] = *(const float4*)&Ab[(size_t)row * KD + kofs + kc];
            }
        }

        // ---- compute on buffer `cur` ----
#pragma unroll
        for (int kk = 0; kk < 4; kk++) {
            unsigned a[2][4], b[4][2];
            const int asw = g * 4;                       // (row&7)*4, row base &7 == g
            const int col0 = (kk * 8 + tig) ^ asw;
            const int col1 = (kk * 8 + 4 + tig) ^ asw;
#pragma unroll
            for (int mi = 0; mi < 2; mi++) {
                int r0 = (wm * 32 + mi * 16 + g) * GBK;
                int r1 = r0 + 8 * GBK;
                a[mi][0] = As[cur][r0 + col0];
                a[mi][1] = As[cur][r1 + col0];
                a[mi][2] = As[cur][r0 + col1];
                a[mi][3] = As[cur][r1 + col1];
            }
            const unsigned* Bp0 = Bs[cur] + (kk * 8 + tig) * GBN;
            const unsigned* Bp1 = Bs[cur] + (kk * 8 + tig + 4) * GBN;
            const int cb = wn * 32 + g, sw = tig * 8;
#pragma unroll
            for (int ni = 0; ni < 4; ni++) {
                b[ni][0] = Bp0[(cb + ni * 8) ^ sw];
                b[ni][1] = Bp1[(cb + ni * 8) ^ sw];
            }
#pragma unroll
            for (int mi = 0; mi < 2; mi++)
#pragma unroll
                for (int ni = 0; ni < 4; ni++)
                    MMA_TF32(acc[mi][ni], a[mi], b[ni]);
        }

        if (t + 1 < GNT) {
            const int nxt = cur ^ 1;
#pragma unroll
            for (int i = 0; i < 4; i++) {
                int idx = tid + i * 256, row = idx >> 5, c4 = idx & 31;
                int col = (c4 * 4) ^ ((row & 3) * 8);
                uint4 v = make_uint4(f2tf(breg[i].x), f2tf(breg[i].y), f2tf(breg[i].z), f2tf(breg[i].w));
                *(uint4*)&Bs[nxt][row * GBN + col] = v;
            }
#pragma unroll
            for (int i = 0; i < 2; i++) {
                int idx = tid * 2 + i, row = idx >> 3, kc = (idx & 7) * 4;
                int col = kc ^ ((row & 7) * 4);
                uint4 v = make_uint4(f2tf(areg[i].x), f2tf(areg[i].y), f2tf(areg[i].z), f2tf(areg[i].w));
                *(uint4*)&As[nxt][row * GBK + col] = v;
            }
            __syncthreads();
        }
    }

    // ---- epilogue ----
#pragma unroll
    for (int mi = 0; mi < 2; mi++) {
        int m = m0 + wm * 32 + mi * 16 + g;
#pragma unroll
        for (int ni = 0; ni < 4; ni++) {
            int n = n0 + wn * 32 + ni * 8 + tig * 2;
            float2 v0 = make_float2(acc[mi][ni][0], acc[mi][ni][1]);
            float2 v1 = make_float2(acc[mi][ni][2], acc[mi][ni][3]);
            *(float2*)&Cb[(size_t)m * N + n]       = v0;
            *(float2*)&Cb[(size_t)(m + 8) * N + n] = v1;
        }
    }
}

// ---------------------------------------------------------------------------
// Depthwise 3x3, SAME zero padding. 8 output rows per block, 256 threads.
// smem band of 10 input rows; lane-strided columns -> conflict-free LDS.
// ---------------------------------------------------------------------------
#define DWR 8
__global__ __launch_bounds__(256) void dw_kernel(
    const float* __restrict__ in, float* __restrict__ out, const float* __restrict__ wdw)
{
    const int band = blockIdx.x;           // 0..15
    const int bc   = blockIdx.y;           // 0..NB*C3-1
    const int ch   = bc % C3;
    const int tid  = threadIdx.x;
    const int y0   = band * DWR;

    __shared__ float s[DWR + 2][WW + 4];   // cols 0..129 used; [c+1] holds col c
    const float* base = in + (size_t)bc * HW;

    // load 10 rows x 128 cols = 320 float4
#pragma unroll
    for (int i = tid; i < 10 * 32; i += 256) {
        int r = i >> 5, c4 = i & 31;
        int yy = y0 - 1 + r;
        float4 v = (yy >= 0 && yy < HH) ? *(const float4*)&base[yy * WW + c4 * 4]
                                        : make_float4(0.f, 0.f, 0.f, 0.f);
        s[r][c4 * 4 + 1] = v.x;
        s[r][c4 * 4 + 2] = v.y;
        s[r][c4 * 4 + 3] = v.z;
        s[r][c4 * 4 + 4] = v.w;
    }
    if (tid < 10) { s[tid][0] = 0.f; s[tid][WW + 1] = 0.f; }

    float w[9];
#pragma unroll
    for (int i = 0; i < 9; i++) w[i] = __ldg(&wdw[ch * 9 + i]);
    __syncthreads();

    const int r    = tid >> 5;       // output row within band
    const int lane = tid & 31;
    float* orow = out + (size_t)bc * HW + (y0 + r) * WW;

#pragma unroll
    for (int j = 0; j < 4; j++) {
        int c = lane + j * 32;       // output col
        float acc = 0.f;
#pragma unroll
        for (int dy = 0; dy < 3; dy++)
#pragma unroll
            for (int dx = 0; dx < 3; dx++)
                acc += w[dy * 3 + dx] * s[r + dy][c + dx];
        orow[c] = acc;
    }
}

// ---------------------------------------------------------------------------
// Score partials: per (split, b, head) accumulate 48x48 Q.K^T over an s-range,
// plus per-row sum-of-squares for q and k.
// ---------------------------------------------------------------------------
__global__ __launch_bounds__(256) void score_partial_kernel(const float* __restrict__ qkvd)
{
    int split = blockIdx.x;
    int unit  = blockIdx.y;
    int b = unit >> 2, hd = unit & 3;
    const float* qb = qkvd + ((size_t)b * C3 + hd * CH) * HW;
    const float* kb = qb + (size_t)C * HW;

    const int CS = 32;
    __shared__ float qs[CH][CS + 1], ks[CH][CS + 1];

    int tid = threadIdx.x, tx = tid & 15, ty = tid >> 4;
    float acc[3][3] = {{0.f,0.f,0.f},{0.f,0.f,0.f},{0.f,0.f,0.f}};
    float nacc = 0.f;

    int s_beg = split * (HW / SPLIT);
    int s_end = s_beg + (HW / SPLIT);
    for (int s0 = s_beg; s0 < s_end; s0 += CS) {
#pragma unroll
        for (int i = 0; i < (CH * CS) / 256; i++) {
            int idx = tid + i * 256;
            int r = idx >> 5, c = idx & 31;
            qs[r][c] = qb[(size_t)r * HW + s0 + c];
            ks[r][c] = kb[(size_t)r * HW + s0 + c];
        }
        __syncthreads();

        if (tid < 2 * CH) {
            int r = (tid < CH) ? tid : (tid - CH);
            const float* row = (tid < CH) ? qs[r] : ks[r];
#pragma unroll
            for (int j = 0; j < CS; j++) { float v = row[j]; nacc += v * v; }
        }

#pragma unroll 4
        for (int j = 0; j < CS; j++) {
            float q0 = qs[3 * ty + 0][j], q1 = qs[3 * ty + 1][j], q2 = qs[3 * ty + 2][j];
            float k0 = ks[3 * tx + 0][j], k1 = ks[3 * tx + 1][j], k2 = ks[3 * tx + 2][j];
            acc[0][0] += q0 * k0; acc[0][1] += q0 * k1; acc[0][2] += q0 * k2;
            acc[1][0] += q1 * k0; acc[1][1] += q1 * k1; acc[1][2] += q1 * k2;
            acc[2][0] += q2 * k0; acc[2][1] += q2 * k1; acc[2][2] += q2 * k2;
        }
        __syncthreads();
    }

    float* part = g_part + ((size_t)split * NB * NH + unit) * PART_STRIDE;
#pragma unroll
    for (int i = 0; i < 3; i++)
#pragma unroll
        for (int j = 0; j < 3; j++)
            part[(3 * ty + i) * CH + (3 * tx + j)] = acc[i][j];
    if (tid < 2 * CH) part[CH * CH + tid] = nacc;
}

// ---------------------------------------------------------------------------
// Reduce partials, apply 1/(|q||k|) * temperature, row softmax. 32 blocks.
// ---------------------------------------------------------------------------
__global__ __launch_bounds__(256) void softmax_kernel(const float* __restrict__ temperature)
{
    int unit = blockIdx.x;
    int hd = unit & 3;
    __shared__ float S[CH][CH];
    __shared__ float rq[CH], rk[CH];
    int tid = threadIdx.x;

    for (int e = tid; e < CH * CH; e += 256) {
        float s = 0.f;
#pragma unroll
        for (int p = 0; p < SPLIT; p++)
            s += g_part[((size_t)p * NB * NH + unit) * PART_STRIDE + e];
        S[e / CH][e % CH] = s;
    }
    if (tid < 2 * CH) {
        float s = 0.f;
#pragma unroll
        for (int p = 0; p < SPLIT; p++)
            s += g_part[((size_t)p * NB * NH + unit) * PART_STRIDE + CH * CH + tid];
        float inv = 1.f / fmaxf(sqrtf(s), 1e-12f);
        if (tid < CH) rq[tid] = inv; else rk[tid - CH] = inv;
    }
    __syncthreads();

    float temp = temperature[hd];
    if (tid < CH) {
        int i = tid;
        float row[CH];
        float mx = -3.402823466e38f;
#pragma unroll
        for (int j = 0; j < CH; j++) {
            float v = S[i][j] * rq[i] * rk[j] * temp;
            row[j] = v;
            mx = fmaxf(mx, v);
        }
        float sum = 0.f;
#pragma unroll
        for (int j = 0; j < CH; j++) { row[j] = expf(row[j] - mx); sum += row[j]; }
        float inv = 1.f / sum;
#pragma unroll
        for (int j = 0; j < CH; j++)
            g_score[(size_t)unit * CH * CH + i * CH + j] = row[j] * inv;
    }
}

// ---------------------------------------------------------------------------
// out[c,s] = sum_d score[c,d] * v[d,s].  Grid (HW/128 tiles, 32 units).
// ---------------------------------------------------------------------------
__global__ __launch_bounds__(256) void attnout_kernel(const float* __restrict__ qkvd)
{
    const int TS = 128;
    int unit = blockIdx.y;
    int b = unit >> 2, hd = unit & 3;
    int s0 = blockIdx.x * TS;
    const float* vb = qkvd + ((size_t)b * C3 + 2 * C + hd * CH) * HW;
    float* ob = g_attn + ((size_t)b * C + hd * CH) * HW;

    __shared__ float sc[CH][CH];
    __shared__ float vs[CH][TS];
    int tid = threadIdx.x, tx = tid & 15, ty = tid >> 4;

    for (int e = tid; e < CH * CH; e += 256)
        sc[e / CH][e % CH] = g_score[(size_t)unit * CH * CH + e];
    for (int idx = tid; idx < CH * TS / 4; idx += 256) {
        int r = idx >> 5, c = idx & 31;
        *(float4*)&vs[r][c * 4] = *(const float4*)&vb[(size_t)r * HW + s0 + c * 4];
    }
    __syncthreads();

    float acc[3][8];
#pragma unroll
    for (int i = 0; i < 3; i++)
#pragma unroll
        for (int j = 0; j < 8; j++) acc[i][j] = 0.f;

#pragma unroll 4
    for (int d = 0; d < CH; d++) {
        float a0 = sc[3 * ty + 0][d], a1 = sc[3 * ty + 1][d], a2 = sc[3 * ty + 2][d];
        float bv[8];
        *(float4*)&bv[0] = *(float4*)&vs[d][tx * 4];
        *(float4*)&bv[4] = *(float4*)&vs[d][64 + tx * 4];
#pragma unroll
        for (int j = 0; j < 8; j++) {
            acc[0][j] += a0 * bv[j];
            acc[1][j] += a1 * bv[j];
            acc[2][j] += a2 * bv[j];
        }
    }

#pragma unroll
    for (int i = 0; i < 3; i++) {
        int cch = 3 * ty + i;
        *(float4*)&ob[(size_t)cch * HW + s0 + tx * 4]      = *(float4*)&acc[i][0];
        *(float4*)&ob[(size_t)cch * HW + s0 + 64 + tx * 4] = *(float4*)&acc[i][4];
    }
}

// ---------------------------------------------------------------------------
extern "C" void kernel_launch(void* const* d_in, const int* in_sizes, int n_in,
                              void* d_out, int out_size)
{
    (void)in_sizes; (void)n_in; (void)out_size;
    const float* x      = (const float*)d_in[0];
    const float* w_qkv  = (const float*)d_in[1];
    const float* w_dw   = (const float*)d_in[2];
    const float* w_proj = (const float*)d_in[3];
    const float* temp   = (const float*)d_in[4];
    float* out = (float*)d_out;

    float *qkv, *dwb, *attn;
    cudaGetSymbolAddress((void**)&qkv,  g_qkv);
    cudaGetSymbolAddress((void**)&dwb,  g_dw);
    cudaGetSymbolAddress((void**)&attn, g_attn);

    // 1) qkv = W_qkv (576x192) * x[b] (192x16384)  — TF32 tensor cores
    gemm_tf32_kernel<<<dim3(HW / GBN, C3 / GBM, NB), 256>>>(w_qkv, x, qkv, C3, HW);
    // 2) depthwise 3x3 (8 rows per block)
    dw_kernel<<<dim3(HH / DWR, NB * C3), 256>>>(qkv, dwb, w_dw);
    // 3) split-K score partials
    score_partial_kernel<<<dim3(SPLIT, NB * NH), 256>>>(dwb);
    // 4) normalize + temperature + softmax
    softmax_kernel<<<NB * NH, 256>>>(temp);
    // 5) attention output = score @ v
    attnout_kernel<<<dim3(HW / 128, NB * NH), 256>>>(dwb);
    // 6) out = W_proj (192x192) * attn[b]  — TF32 tensor cores
    gemm_tf32_kernel<<<dim3(HW / GBN, C / GBM, NB), 256>>>(w_proj, attn, out, C, HW);
}

// round 5
// speedup vs baseline: 2.5410x; 1.1146x over previous
#include <cuda_runtime.h>
#include <math.h>

#define NB 8
#define C 192
#define C3 576
#define NH 4
#define CH 48
#define HH 128
#define WW 128
#define HW 16384
#define SPLIT 32
#define PART_STRIDE (CH*CH + 2*CH)   /* 2400 */

// Scratch (device globals: no allocation allowed in kernel_launch)
__device__ float g_qkv [NB*C3*HW];                 // 302 MB: 1x1 conv output
__device__ float g_dw  [NB*C3*HW];                 // 302 MB: depthwise output
__device__ float g_part[SPLIT*NB*NH*PART_STRIDE];  // split-K partials
__device__ float g_score[NB*NH*CH*CH];             // softmaxed scores
__device__ float g_P   [NB*C*C];                   // fused W_proj @ blockdiag(score)

// ===========================================================================
// Tensor-core TF32 GEMM: C[z] = A[z] * B[z]
// A [M,K=192] row-major (astride per batch; 0 = shared), B row-major
// (bstride per batch), C [M,N]. BM=64, BN=128, BK=32, 256 threads,
// warp tile 32x32, double-buffered smem (48KB exactly).
// ===========================================================================
#define GBM 64
#define GBN 128
#define GBK 32
#define KD  192
#define GNT (KD/GBK)   /* 6 */

__device__ __forceinline__ unsigned f2tf(float f) {
    unsigned u; asm("cvt.rna.tf32.f32 %0, %1;" : "=r"(u) : "f"(f)); return u;
}

#define MMA_TF32(d, av, bv)                                                   \
  asm("mma.sync.aligned.m16n8k8.row.col.f32.tf32.tf32.f32 "                   \
      "{%0,%1,%2,%3}, {%4,%5,%6,%7}, {%8,%9}, {%0,%1,%2,%3};"                 \
      : "+f"(d[0]), "+f"(d[1]), "+f"(d[2]), "+f"(d[3])                        \
      : "r"(av[0]), "r"(av[1]), "r"(av[2]), "r"(av[3]),                       \
        "r"(bv[0]), "r"(bv[1]))

__global__ __launch_bounds__(256) void gemm_tf32_kernel(
    const float* __restrict__ A, const float* __restrict__ Bm, float* __restrict__ Cm,
    int M, int N, size_t astride, size_t bstride)
{
    __shared__ unsigned As[2][GBM * GBK];    // [m][k^((m&7)*4)], stride 32
    __shared__ unsigned Bs[2][GBK * GBN];    // [k][n], XOR-8 swizzled on n

    const int tid  = threadIdx.x;
    const int lane = tid & 31, wid = tid >> 5;
    const int wm = wid & 1, wn = wid >> 1;       // 2 x 4 warps
    const int g = lane >> 2, tig = lane & 3;

    const int m0 = blockIdx.y * GBM, n0 = blockIdx.x * GBN;
    const float* Ab = A + astride * blockIdx.z + (size_t)m0 * KD;
    const float* Bb = Bm + bstride * blockIdx.z + n0;
    float*       Cb = Cm + (size_t)blockIdx.z * M * N;

    float acc[2][4][4];
#pragma unroll
    for (int mi = 0; mi < 2; mi++)
#pragma unroll
        for (int ni = 0; ni < 4; ni++)
#pragma unroll
            for (int j = 0; j < 4; j++) acc[mi][ni][j] = 0.f;

    float4 areg[2];   // A: 2 float4 per thread (64x32 tile)
    float4 breg[4];   // B: 4 float4 per thread (32x128 tile)

    // prologue: LDG tile 0 + STS into buffer 0
#pragma unroll
    for (int i = 0; i < 2; i++) {
        int idx = tid * 2 + i, row = idx >> 3, kc = (idx & 7) * 4;
        areg[i] = *(const float4*)&Ab[(size_t)row * KD + kc];
    }
#pragma unroll
    for (int i = 0; i < 4; i++) {
        int idx = tid + i * 256, row = idx >> 5, c4 = idx & 31;
        breg[i] = *(const float4*)&Bb[(size_t)row * N + c4 * 4];
    }
#pragma unroll
    for (int i = 0; i < 2; i++) {
        int idx = tid * 2 + i, row = idx >> 3, kc = (idx & 7) * 4;
        int col = kc ^ ((row & 7) * 4);
        uint4 v = make_uint4(f2tf(areg[i].x), f2tf(areg[i].y), f2tf(areg[i].z), f2tf(areg[i].w));
        *(uint4*)&As[0][row * GBK + col] = v;
    }
#pragma unroll
    for (int i = 0; i < 4; i++) {
        int idx = tid + i * 256, row = idx >> 5, c4 = idx & 31;
        int col = (c4 * 4) ^ ((row & 3) * 8);
        uint4 v = make_uint4(f2tf(breg[i].x), f2tf(breg[i].y), f2tf(breg[i].z), f2tf(breg[i].w));
        *(uint4*)&Bs[0][row * GBN + col] = v;
    }
    __syncthreads();

#pragma unroll
    for (int t = 0; t < GNT; t++) {
        const int cur = t & 1;
        if (t + 1 < GNT) {
            int kofs = (t + 1) * GBK;
#pragma unroll
            for (int i = 0; i < 4; i++) {
                int idx = tid + i * 256, row = idx >> 5, c4 = idx & 31;
                breg[i] = *(const float4*)&Bb[(size_t)(kofs + row) * N + c4 * 4];
            }
#pragma unroll
            for (int i = 0; i < 2; i++) {
                int idx = tid * 2 + i, row = idx >> 3, kc = (idx & 7) * 4;
                areg[i] = *(const float4*)&Ab[(size_t)row * KD + kofs + kc];
            }
        }

        // ---- compute on buffer `cur` ----
#pragma unroll
        for (int kk = 0; kk < 4; kk++) {
            unsigned a[2][4], b[4][2];
            const int asw = g * 4;
            const int col0 = (kk * 8 + tig) ^ asw;
            const int col1 = (kk * 8 + 4 + tig) ^ asw;
#pragma unroll
            for (int mi = 0; mi < 2; mi++) {
                int r0 = (wm * 32 + mi * 16 + g) * GBK;
                int r1 = r0 + 8 * GBK;
                a[mi][0] = As[cur][r0 + col0];
                a[mi][1] = As[cur][r1 + col0];
                a[mi][2] = As[cur][r0 + col1];
                a[mi][3] = As[cur][r1 + col1];
            }
            const unsigned* Bp0 = Bs[cur] + (kk * 8 + tig) * GBN;
            const unsigned* Bp1 = Bs[cur] + (kk * 8 + tig + 4) * GBN;
            const int cb = wn * 32 + g, sw = tig * 8;
#pragma unroll
            for (int ni = 0; ni < 4; ni++) {
                b[ni][0] = Bp0[(cb + ni * 8) ^ sw];
                b[ni][1] = Bp1[(cb + ni * 8) ^ sw];
            }
#pragma unroll
            for (int mi = 0; mi < 2; mi++)
#pragma unroll
                for (int ni = 0; ni < 4; ni++)
                    MMA_TF32(acc[mi][ni], a[mi], b[ni]);
        }

        if (t + 1 < GNT) {
            const int nxt = cur ^ 1;
#pragma unroll
            for (int i = 0; i < 4; i++) {
                int idx = tid + i * 256, row = idx >> 5, c4 = idx & 31;
                int col = (c4 * 4) ^ ((row & 3) * 8);
                uint4 v = make_uint4(f2tf(breg[i].x), f2tf(breg[i].y), f2tf(breg[i].z), f2tf(breg[i].w));
                *(uint4*)&Bs[nxt][row * GBN + col] = v;
            }
#pragma unroll
            for (int i = 0; i < 2; i++) {
                int idx = tid * 2 + i, row = idx >> 3, kc = (idx & 7) * 4;
                int col = kc ^ ((row & 7) * 4);
                uint4 v = make_uint4(f2tf(areg[i].x), f2tf(areg[i].y), f2tf(areg[i].z), f2tf(areg[i].w));
                *(uint4*)&As[nxt][row * GBK + col] = v;
            }
            __syncthreads();
        }
    }

    // ---- epilogue ----
#pragma unroll
    for (int mi = 0; mi < 2; mi++) {
        int m = m0 + wm * 32 + mi * 16 + g;
#pragma unroll
        for (int ni = 0; ni < 4; ni++) {
            int n = n0 + wn * 32 + ni * 8 + tig * 2;
            float2 v0 = make_float2(acc[mi][ni][0], acc[mi][ni][1]);
            float2 v1 = make_float2(acc[mi][ni][2], acc[mi][ni][3]);
            *(float2*)&Cb[(size_t)m * N + n]       = v0;
            *(float2*)&Cb[(size_t)(m + 8) * N + n] = v1;
        }
    }
}

// ---------------------------------------------------------------------------
// Depthwise 3x3, SAME zero padding. 8 output rows per block, 256 threads.
// ---------------------------------------------------------------------------
#define DWR 8
__global__ __launch_bounds__(256) void dw_kernel(
    const float* __restrict__ in, float* __restrict__ out, const float* __restrict__ wdw)
{
    const int band = blockIdx.x;           // 0..15
    const int bc   = blockIdx.y;           // 0..NB*C3-1
    const int ch   = bc % C3;
    const int tid  = threadIdx.x;
    const int y0   = band * DWR;

    __shared__ float s[DWR + 2][WW + 4];
    const float* base = in + (size_t)bc * HW;

#pragma unroll
    for (int i = tid; i < 10 * 32; i += 256) {
        int r = i >> 5, c4 = i & 31;
        int yy = y0 - 1 + r;
        float4 v = (yy >= 0 && yy < HH) ? *(const float4*)&base[yy * WW + c4 * 4]
                                        : make_float4(0.f, 0.f, 0.f, 0.f);
        s[r][c4 * 4 + 1] = v.x;
        s[r][c4 * 4 + 2] = v.y;
        s[r][c4 * 4 + 3] = v.z;
        s[r][c4 * 4 + 4] = v.w;
    }
    if (tid < 10) { s[tid][0] = 0.f; s[tid][WW + 1] = 0.f; }

    float w[9];
#pragma unroll
    for (int i = 0; i < 9; i++) w[i] = __ldg(&wdw[ch * 9 + i]);
    __syncthreads();

    const int r    = tid >> 5;
    const int lane = tid & 31;
    float* orow = out + (size_t)bc * HW + (y0 + r) * WW;

#pragma unroll
    for (int j = 0; j < 4; j++) {
        int c = lane + j * 32;
        float acc = 0.f;
#pragma unroll
        for (int dy = 0; dy < 3; dy++)
#pragma unroll
            for (int dx = 0; dx < 3; dx++)
                acc += w[dy * 3 + dx] * s[r + dy][c + dx];
        orow[c] = acc;
    }
}

// ---------------------------------------------------------------------------
// Score partials: per (split, b, head) accumulate 48x48 Q.K^T over an s-range,
// plus per-row sum-of-squares for q and k.
// ---------------------------------------------------------------------------
__global__ __launch_bounds__(256) void score_partial_kernel(const float* __restrict__ qkvd)
{
    int split = blockIdx.x;
    int unit  = blockIdx.y;
    int b = unit >> 2, hd = unit & 3;
    const float* qb = qkvd + ((size_t)b * C3 + hd * CH) * HW;
    const float* kb = qb + (size_t)C * HW;

    const int CS = 32;
    __shared__ float qs[CH][CS + 1], ks[CH][CS + 1];

    int tid = threadIdx.x, tx = tid & 15, ty = tid >> 4;
    float acc[3][3] = {{0.f,0.f,0.f},{0.f,0.f,0.f},{0.f,0.f,0.f}};
    float nacc = 0.f;

    int s_beg = split * (HW / SPLIT);
    int s_end = s_beg + (HW / SPLIT);
    for (int s0 = s_beg; s0 < s_end; s0 += CS) {
#pragma unroll
        for (int i = 0; i < (CH * CS) / 256; i++) {
            int idx = tid + i * 256;
            int r = idx >> 5, c = idx & 31;
            qs[r][c] = qb[(size_t)r * HW + s0 + c];
            ks[r][c] = kb[(size_t)r * HW + s0 + c];
        }
        __syncthreads();

        if (tid < 2 * CH) {
            int r = (tid < CH) ? tid : (tid - CH);
            const float* row = (tid < CH) ? qs[r] : ks[r];
#pragma unroll
            for (int j = 0; j < CS; j++) { float v = row[j]; nacc += v * v; }
        }

#pragma unroll 4
        for (int j = 0; j < CS; j++) {
            float q0 = qs[3 * ty + 0][j], q1 = qs[3 * ty + 1][j], q2 = qs[3 * ty + 2][j];
            float k0 = ks[3 * tx + 0][j], k1 = ks[3 * tx + 1][j], k2 = ks[3 * tx + 2][j];
            acc[0][0] += q0 * k0; acc[0][1] += q0 * k1; acc[0][2] += q0 * k2;
            acc[1][0] += q1 * k0; acc[1][1] += q1 * k1; acc[1][2] += q1 * k2;
            acc[2][0] += q2 * k0; acc[2][1] += q2 * k1; acc[2][2] += q2 * k2;
        }
        __syncthreads();
    }

    float* part = g_part + ((size_t)split * NB * NH + unit) * PART_STRIDE;
#pragma unroll
    for (int i = 0; i < 3; i++)
#pragma unroll
        for (int j = 0; j < 3; j++)
            part[(3 * ty + i) * CH + (3 * tx + j)] = acc[i][j];
    if (tid < 2 * CH) part[CH * CH + tid] = nacc;
}

// ---------------------------------------------------------------------------
// Reduce partials, apply 1/(|q||k|) * temperature, row softmax. 32 blocks.
// ---------------------------------------------------------------------------
__global__ __launch_bounds__(256) void softmax_kernel(const float* __restrict__ temperature)
{
    int unit = blockIdx.x;
    int hd = unit & 3;
    __shared__ float S[CH][CH];
    __shared__ float rq[CH], rk[CH];
    int tid = threadIdx.x;

    for (int e = tid; e < CH * CH; e += 256) {
        float s = 0.f;
#pragma unroll
        for (int p = 0; p < SPLIT; p++)
            s += g_part[((size_t)p * NB * NH + unit) * PART_STRIDE + e];
        S[e / CH][e % CH] = s;
    }
    if (tid < 2 * CH) {
        float s = 0.f;
#pragma unroll
        for (int p = 0; p < SPLIT; p++)
            s += g_part[((size_t)p * NB * NH + unit) * PART_STRIDE + CH * CH + tid];
        float inv = 1.f / fmaxf(sqrtf(s), 1e-12f);
        if (tid < CH) rq[tid] = inv; else rk[tid - CH] = inv;
    }
    __syncthreads();

    float temp = temperature[hd];
    if (tid < CH) {
        int i = tid;
        float row[CH];
        float mx = -3.402823466e38f;
#pragma unroll
        for (int j = 0; j < CH; j++) {
            float v = S[i][j] * rq[i] * rk[j] * temp;
            row[j] = v;
            mx = fmaxf(mx, v);
        }
        float sum = 0.f;
#pragma unroll
        for (int j = 0; j < CH; j++) { row[j] = expf(row[j] - mx); sum += row[j]; }
        float inv = 1.f / sum;
#pragma unroll
        for (int j = 0; j < CH; j++)
            g_score[(size_t)unit * CH * CH + i * CH + j] = row[j] * inv;
    }
}

// ---------------------------------------------------------------------------
// P_b[o, hd*48+d] = sum_c Wproj[o, hd*48+c] * score[b,hd][c,d]
// 32 blocks (one per b,hd), 256 threads, fp32.
// ---------------------------------------------------------------------------
__global__ __launch_bounds__(256) void pmat_kernel(const float* __restrict__ wproj)
{
    int unit = blockIdx.x;
    int b = unit >> 2, hd = unit & 3;
    __shared__ float sc[CH][CH];      // score[c][d]
    __shared__ float wp[C][CH];       // wp[o][c]
    int tid = threadIdx.x;

    for (int e = tid; e < CH * CH; e += 256)
        sc[e / CH][e % CH] = g_score[(size_t)unit * CH * CH + e];
    for (int e = tid; e < C * CH; e += 256) {
        int o = e / CH, c = e % CH;
        wp[o][c] = wproj[o * C + hd * CH + c];
    }
    __syncthreads();

    for (int e = tid; e < C * CH; e += 256) {
        int o = e / CH, d = e % CH;
        float acc = 0.f;
#pragma unroll
        for (int c = 0; c < CH; c++) acc += wp[o][c] * sc[c][d];
        g_P[((size_t)b * C + o) * C + hd * CH + d] = acc;
    }
}

// ---------------------------------------------------------------------------
extern "C" void kernel_launch(void* const* d_in, const int* in_sizes, int n_in,
                              void* d_out, int out_size)
{
    (void)in_sizes; (void)n_in; (void)out_size;
    const float* x      = (const float*)d_in[0];
    const float* w_qkv  = (const float*)d_in[1];
    const float* w_dw   = (const float*)d_in[2];
    const float* w_proj = (const float*)d_in[3];
    const float* temp   = (const float*)d_in[4];
    float* out = (float*)d_out;

    float *qkv, *dwb, *pmat;
    cudaGetSymbolAddress((void**)&qkv,  g_qkv);
    cudaGetSymbolAddress((void**)&dwb,  g_dw);
    cudaGetSymbolAddress((void**)&pmat, g_P);

    // 1) qkv = W_qkv (576x192) * x[b] (192x16384)  — TF32 tensor cores
    gemm_tf32_kernel<<<dim3(HW / GBN, C3 / GBM, NB), 256>>>(
        w_qkv, x, qkv, C3, HW, 0, (size_t)KD * HW);
    // 2) depthwise 3x3 (8 rows per block)
    dw_kernel<<<dim3(HH / DWR, NB * C3), 256>>>(qkv, dwb, w_dw);
    // 3) split-K score partials
    score_partial_kernel<<<dim3(SPLIT, NB * NH), 256>>>(dwb);
    // 4) normalize + temperature + softmax
    softmax_kernel<<<NB * NH, 256>>>(temp);
    // 5) P_b = W_proj @ blockdiag(score_b)   (fp32, tiny)
    pmat_kernel<<<NB * NH, 256>>>(w_proj);
    // 6) out = P_b (192x192) * v[b] (192x16384)  — TF32 tensor cores
    //    v lives at g_dw + 2C*HW within each batch's C3*HW stripe
    gemm_tf32_kernel<<<dim3(HW / GBN, C / GBM, NB), 256>>>(
        pmat, dwb + (size_t)2 * C * HW, out, C, HW,
        (size_t)C * C, (size_t)C3 * HW);
}